// round 14
// baseline (speedup 1.0000x reference)
#include <cuda_runtime.h>
#include <cuda_bf16.h>
#include <math_constants.h>

#define Bsz 1024
#define Ssz 128
#define NW (Bsz*Ssz)   // 131072 words

__device__ __forceinline__ float tanh_fast(float x){ float y; asm("tanh.approx.f32 %0, %1;" : "=f"(y) : "f"(x)); return y; }

// process one (b,s) pair: tag linear + log_softmax with register weights
__device__ __forceinline__ void tag_pair(const float* sH, const float wt[5][12], const float bs[5],
                                         float* __restrict__ out, int blk, int p, int lane)
{
    const unsigned FULL = 0xffffffffu;
    const float4* hp = (const float4*)(sH + p*12);   // 48B stride, aligned, broadcast
    float4 h0v = hp[0], h1v = hp[1], h2v = hp[2];
    float h[12] = {h0v.x,h0v.y,h0v.z,h0v.w, h1v.x,h1v.y,h1v.z,h1v.w,
                   h2v.x,h2v.y,h2v.z,h2v.w};

    // |v| bounded (|h|<1, small weights): safe to skip max-shift
    float tg[5]; float zs = 0.f;
    #pragma unroll
    for (int t5=0; t5<5; t5++){
        float v = bs[t5];
        #pragma unroll
        for (int k=0;k<12;k++) v = fmaf(h[k], wt[t5][k], v);
        tg[t5] = v;
        zs += __expf(v);
    }
    #pragma unroll
    for (int o=16;o>0;o>>=1) zs += __shfl_xor_sync(FULL, zs, o);
    float lse = __logf(zs);

    float* op = out + ((size_t)blk*Ssz + p)*135;
    #pragma unroll
    for (int t5=0; t5<5; t5++){
        int j = lane + 32*t5;
        if (j < 135) op[j] = tg[t5] - lse;
    }
}

// ============ fully fused: one block per sentence, 128 threads ============
// Phase A: 128 threads, 1 word each: char-CNN + emb + 48 xgate pre-acts -> sXG
// Phase B: warps 0/1 = fwd/bwd LSTM -> sH; at step 95 they bar.arrive, so
//          warps 2/3 (weights preloaded) start C on the ready middle pairs
//          32..95 DURING B's tail. After syncthreads, edge pairs split 4 ways.
__global__ __launch_bounds__(128) void fused_tagger(
    const int* __restrict__ word_idx, const int* __restrict__ char_idx,
    const float* __restrict__ word_emb, const float* __restrict__ char_emb,
    const float* __restrict__ Wc, const float* __restrict__ bc,
    const float* __restrict__ Wih_f, const float* __restrict__ b_f,
    const float* __restrict__ Wih_b, const float* __restrict__ b_b,
    const float* __restrict__ Whh_f, const float* __restrict__ Whh_b,
    const float* __restrict__ Wt, const float* __restrict__ bt,
    float* __restrict__ out)
{
    // aliased region: tables (Phase A) / sH (Phase B/C)
    __shared__ __align__(16) char uraw[8064];
    float4* sP = (float4*)uraw;                    // 300 entries (4800 B)
    float4* sW = (float4*)(uraw + 4800);           // 192 entries (3072 B)
    float*  sB = (float*)(uraw + 4800 + 3072);     // 48 floats
    float*  sH = (float*)uraw;                     // [128 steps][12] (after Phase A)

    __shared__ float sXG[Ssz*49];  // [word][49]: gates 0..23 fwd, 24..47 bwd, 1 pad

    const unsigned FULL = 0xffffffffu;
    int tid  = threadIdx.x;
    int lane = tid & 31;
    int warp = tid >> 5;
    int blk  = blockIdx.x;         // sentence

    // ---- hoist per-word global loads (latency overlaps table build) ----
    size_t w = (size_t)blk*Ssz + tid;
    int ci[14];
    const int2* cp = (const int2*)(char_idx + w*14);
    #pragma unroll
    for (int k=0;k<7;k++){ int2 v = __ldg(cp+k); ci[2*k]=v.x; ci[2*k+1]=v.y; }

    float x[16];
    int widx = __ldg(word_idx + w);
    const float2* wep = (const float2*)(word_emb) + (size_t)widx*5;
    #pragma unroll
    for (int k=0;k<5;k++){ float2 v = __ldg(wep+k); x[2*k]=v.x; x[2*k+1]=v.y; }
    x[14]=0.f; x[15]=0.f;

    // ---- build tables ----
    for (int i = tid; i < 300; i += 128){
        int c = i/3, k = i%3;
        float4 acc;
        if (k==0){ acc.x=__ldg(bc+0); acc.y=__ldg(bc+1); acc.z=__ldg(bc+2); acc.w=__ldg(bc+3); }
        else     { acc.x=0.f; acc.y=0.f; acc.z=0.f; acc.w=0.f; }
        #pragma unroll
        for (int m=0;m<6;m++){
            float e = __ldg(char_emb + c*6 + m);
            acc.x = fmaf(e, __ldg(Wc + 0*18 + k*6 + m), acc.x);
            acc.y = fmaf(e, __ldg(Wc + 1*18 + k*6 + m), acc.y);
            acc.z = fmaf(e, __ldg(Wc + 2*18 + k*6 + m), acc.z);
            acc.w = fmaf(e, __ldg(Wc + 3*18 + k*6 + m), acc.w);
        }
        sP[i] = acc;
    }
    for (int i = tid; i < 192; i += 128){
        int g = i >> 2, q = i & 3;
        const float* Wih = (g < 24) ? (Wih_f + g*14) : (Wih_b + (g-24)*14);
        int base = q*4;
        float4 wv;
        wv.x = (base+0 < 14) ? __ldg(Wih+base+0) : 0.f;
        wv.y = (base+1 < 14) ? __ldg(Wih+base+1) : 0.f;
        wv.z = (base+2 < 14) ? __ldg(Wih+base+2) : 0.f;
        wv.w = (base+3 < 14) ? __ldg(Wih+base+3) : 0.f;
        sW[i] = wv;
    }
    if (tid < 48) sB[tid] = (tid < 24) ? __ldg(b_f + tid) : __ldg(b_b + tid - 24);
    __syncthreads();

    // ---- Phase A: conv + maxpool ----
    float4 a = make_float4(-CUDART_INF_F,-CUDART_INF_F,-CUDART_INF_F,-CUDART_INF_F);
    #pragma unroll
    for (int win=0; win<12; win++){
        float4 s0 = sP[ci[win]  *3 + 0];
        float4 s1 = sP[ci[win+1]*3 + 1];
        float4 s2 = sP[ci[win+2]*3 + 2];
        a.x = fmaxf(a.x, s0.x + s1.x + s2.x);
        a.y = fmaxf(a.y, s0.y + s1.y + s2.y);
        a.z = fmaxf(a.z, s0.z + s1.z + s2.z);
        a.w = fmaxf(a.w, s0.w + s1.w + s2.w);
    }
    x[10]=a.x; x[11]=a.y; x[12]=a.z; x[13]=a.w;

    // ---- 48 gate pre-activations -> sXG row (stride 49: conflict-free) ----
    {
        float* st = &sXG[tid*49];
        #pragma unroll
        for (int g=0; g<48; g++){
            float acc = sB[g];
            #pragma unroll
            for (int q=0; q<4; q++){
                float4 wvv = sW[g*4 + q];
                acc = fmaf(x[4*q+0], wvv.x, acc);
                acc = fmaf(x[4*q+1], wvv.y, acc);
                acc = fmaf(x[4*q+2], wvv.z, acc);
                acc = fmaf(x[4*q+3], wvv.w, acc);
            }
            st[g] = acc;
        }
    }
    __syncthreads();   // tables dead below; sH aliases them

    // Phase-C weights (loaded during B by warps 2/3, after B by warps 0/1)
    float wt[5][12], bs[5];

    if (warp < 2){
        // ---- Phase B: fwd/bwd recurrence; lane j<24 owns gate j (i,f,g,o) ----
        int d   = warp;
        int jc  = (lane < 24) ? lane : 0;
        bool is_g = (lane >= 12 && lane < 18);
        float sm = is_g ? 1.f : 0.5f;     // sigmoid(x) = 0.5*tanh(0.5x)+0.5
        float ab = is_g ? 0.f : 0.5f;

        const float* Whh = d ? Whh_b : Whh_f;
        float w0=__ldg(Whh+jc*6+0), w1=__ldg(Whh+jc*6+1), w2=__ldg(Whh+jc*6+2),
              w3=__ldg(Whh+jc*6+3), w4=__ldg(Whh+jc*6+4), w5=__ldg(Whh+jc*6+5);

        const float* xgp = &sXG[d*24];
        float h0=0.f,h1=0.f,h2=0.f,h3=0.f,h4=0.f,h5=0.f,c=0.f;
        int s  = d ? (Ssz-1) : 0;
        int ds = d ? -1 : 1;

        float pf = xgp[s*49 + jc];
        #pragma unroll 4
        for (int t=0; t<Ssz; t++){
            float gcur = pf;
            if (t+1 < Ssz) pf = xgp[(s+ds)*49 + jc];   // one-ahead smem prefetch

            float g = fmaf(w0,h0,gcur);
            g = fmaf(w1,h1,g); g = fmaf(w2,h2,g); g = fmaf(w3,h3,g);
            g = fmaf(w4,h4,g); g = fmaf(w5,h5,g);
            float act = fmaf(sm, tanh_fast(g*sm), ab);

            float af = __shfl_sync(FULL, act, lane+6);
            float ag = __shfl_sync(FULL, act, lane+12);
            float ao = __shfl_sync(FULL, act, lane+18);
            c = fmaf(af, c, act*ag);
            float hj = ao * tanh_fast(c);

            h0=__shfl_sync(FULL,hj,0); h1=__shfl_sync(FULL,hj,1); h2=__shfl_sync(FULL,hj,2);
            h3=__shfl_sync(FULL,hj,3); h4=__shfl_sync(FULL,hj,4); h5=__shfl_sync(FULL,hj,5);

            if (lane < 6) sH[s*12 + d*6 + lane] = hj;
            s += ds;

            if (t == 95){
                // pairs 32..95 are now complete in sH: release warps 2/3
                __threadfence_block();
                asm volatile("bar.arrive 1, 128;");
            }
        }
        // load C weights after the recurrence (overlaps other warps' C work)
        #pragma unroll
        for (int t5=0; t5<5; t5++){
            int j = lane + 32*t5;
            bool valid = (j < 135);
            bs[t5] = valid ? __ldg(bt + j) : -1e30f;   // exp(-1e30)=0
            #pragma unroll
            for (int k=0;k<12;k++) wt[t5][k] = valid ? __ldg(Wt + j*12 + k) : 0.f;
        }
    } else {
        // warps 2/3: preload C weights during the recurrence window
        #pragma unroll
        for (int t5=0; t5<5; t5++){
            int j = lane + 32*t5;
            bool valid = (j < 135);
            bs[t5] = valid ? __ldg(bt + j) : -1e30f;
            #pragma unroll
            for (int k=0;k<12;k++) wt[t5][k] = valid ? __ldg(Wt + j*12 + k) : 0.f;
        }
        // wait for middle pairs, then process them while B finishes its tail
        asm volatile("bar.sync 1, 128;");
        int base = 32 + (warp-2)*32;    // warp2: 32..63, warp3: 64..95
        #pragma unroll 2
        for (int it=0; it<32; it++)
            tag_pair(sH, wt, bs, out, blk, base+it, lane);
    }
    __syncthreads();

    // ---- edge pairs [0..31] + [96..127], split across all 4 warps ----
    #pragma unroll 2
    for (int it=0; it<16; it++){
        int e = warp*16 + it;           // 0..63
        int p = (e < 32) ? e : e + 64;
        tag_pair(sH, wt, bs, out, blk, p, lane);
    }
}

// ---------------- Launch ----------------
extern "C" void kernel_launch(void* const* d_in, const int* in_sizes, int n_in,
                              void* d_out, int out_size)
{
    const int *word_idx=nullptr,*char_idx=nullptr;
    const float *word_emb=nullptr,*char_emb=nullptr,*Wc=nullptr,*bc=nullptr,
        *Wih_f=nullptr,*Whh_f=nullptr,*b_f=nullptr,
        *Wih_b=nullptr,*Whh_b=nullptr,*b_b=nullptr,*Wt=nullptr,*bt=nullptr;
    for (int i=0;i<n_in;i++){
        int sz = in_sizes[i]; const void* p = d_in[i];
        switch (sz){
            case 131072:  word_idx=(const int*)p; break;          // [B,S]
            case 1835008: char_idx=(const int*)p; break;          // [B,S,LP]
            case 500000:  word_emb=(const float*)p; break;        // [V,WE]
            case 600:     char_emb=(const float*)p; break;        // [A,CE]
            case 72:      Wc=(const float*)p; break;              // [Lf,K*CE]
            case 4:       bc=(const float*)p; break;              // [Lf]
            case 336:     if(!Wih_f) Wih_f=(const float*)p; else Wih_b=(const float*)p; break;
            case 144:     if(!Whh_f) Whh_f=(const float*)p; else Whh_b=(const float*)p; break;
            case 24:      if(!b_f)   b_f  =(const float*)p; else b_b  =(const float*)p; break;
            case 1620:    Wt=(const float*)p; break;              // [T,2H]
            case 135:     bt=(const float*)p; break;              // [T]
        }
    }

    fused_tagger<<<Bsz, 128>>>(word_idx, char_idx, word_emb, char_emb,
                               Wc, bc, Wih_f, b_f, Wih_b, b_b,
                               Whh_f, Whh_b, Wt, bt, (float*)d_out);
    (void)out_size; (void)n_in;
}

// round 15
// speedup vs baseline: 1.2175x; 1.2175x over previous
#include <cuda_runtime.h>
#include <cuda_fp16.h>
#include <math_constants.h>

#define Bsz 1024
#define Ssz 128
#define NW (Bsz*Ssz)   // 131072 words

__device__ __forceinline__ float tanh_fast(float x){ float y; asm("tanh.approx.f32 %0, %1;" : "=f"(y) : "f"(x)); return y; }

// ============ fully fused: TWO sentences per 128-thread block ============
// Phase A: 128 threads x 2 words: char-CNN + emb + 48 xgate pre-acts -> sXG (fp16)
// Phase B: ALL 4 warps run LSTM chains (2 sentences x 2 dirs) -> sH (aliases tables)
// Phase C: 4 warps x 64 pairs: tag linear + log_softmax -> out (unroll 2)
__global__ __launch_bounds__(128) void fused_tagger(
    const int* __restrict__ word_idx, const int* __restrict__ char_idx,
    const float* __restrict__ word_emb, const float* __restrict__ char_emb,
    const float* __restrict__ Wc, const float* __restrict__ bc,
    const float* __restrict__ Wih_f, const float* __restrict__ b_f,
    const float* __restrict__ Wih_b, const float* __restrict__ b_b,
    const float* __restrict__ Whh_f, const float* __restrict__ Whh_b,
    const float* __restrict__ Wt, const float* __restrict__ bt,
    float* __restrict__ out)
{
    // aliased region: tables (Phase A) / sH[2][128][12] (Phase B/C)
    __shared__ __align__(16) char uraw[12288];
    float4* sP = (float4*)uraw;                    // 300 entries (4800 B)
    float4* sW = (float4*)(uraw + 4800);           // 192 entries (3072 B)
    float*  sB = (float*)(uraw + 4800 + 3072);     // 48 floats
    float*  sH = (float*)uraw;                     // [2][128][12] floats (after A)

    __shared__ __half sXG[2*Ssz*50];  // [sent][word][50]: 0..23 fwd, 24..47 bwd, 2 pad

    const unsigned FULL = 0xffffffffu;
    int tid  = threadIdx.x;
    int lane = tid & 31;
    int warp = tid >> 5;
    int blk  = blockIdx.x;         // sentences 2*blk, 2*blk+1

    // ---- build tables ----
    for (int i = tid; i < 300; i += 128){
        int c = i/3, k = i%3;
        float4 acc;
        if (k==0){ acc.x=__ldg(bc+0); acc.y=__ldg(bc+1); acc.z=__ldg(bc+2); acc.w=__ldg(bc+3); }
        else     { acc.x=0.f; acc.y=0.f; acc.z=0.f; acc.w=0.f; }
        #pragma unroll
        for (int m=0;m<6;m++){
            float e = __ldg(char_emb + c*6 + m);
            acc.x = fmaf(e, __ldg(Wc + 0*18 + k*6 + m), acc.x);
            acc.y = fmaf(e, __ldg(Wc + 1*18 + k*6 + m), acc.y);
            acc.z = fmaf(e, __ldg(Wc + 2*18 + k*6 + m), acc.z);
            acc.w = fmaf(e, __ldg(Wc + 3*18 + k*6 + m), acc.w);
        }
        sP[i] = acc;
    }
    for (int i = tid; i < 192; i += 128){
        int g = i >> 2, q = i & 3;
        const float* Wih = (g < 24) ? (Wih_f + g*14) : (Wih_b + (g-24)*14);
        int base = q*4;
        float4 wv;
        wv.x = (base+0 < 14) ? __ldg(Wih+base+0) : 0.f;
        wv.y = (base+1 < 14) ? __ldg(Wih+base+1) : 0.f;
        wv.z = (base+2 < 14) ? __ldg(Wih+base+2) : 0.f;
        wv.w = (base+3 < 14) ? __ldg(Wih+base+3) : 0.f;
        sW[i] = wv;
    }
    if (tid < 48) sB[tid] = (tid < 24) ? __ldg(b_f + tid) : __ldg(b_b + tid - 24);
    __syncthreads();

    // ---- Phase A: 2 words per thread (word tid of each sentence) ----
    #pragma unroll 1
    for (int wv2 = 0; wv2 < 2; wv2++){
        size_t w = (size_t)blk*2*Ssz + wv2*Ssz + tid;

        int ci[14];
        const int2* cp = (const int2*)(char_idx + w*14);
        #pragma unroll
        for (int k=0;k<7;k++){ int2 v = __ldg(cp+k); ci[2*k]=v.x; ci[2*k+1]=v.y; }

        float x[16];
        int widx = __ldg(word_idx + w);
        const float2* wep = (const float2*)(word_emb) + (size_t)widx*5;
        #pragma unroll
        for (int k=0;k<5;k++){ float2 v = __ldg(wep+k); x[2*k]=v.x; x[2*k+1]=v.y; }
        x[14]=0.f; x[15]=0.f;

        float4 a = make_float4(-CUDART_INF_F,-CUDART_INF_F,-CUDART_INF_F,-CUDART_INF_F);
        #pragma unroll
        for (int win=0; win<12; win++){
            float4 s0 = sP[ci[win]  *3 + 0];
            float4 s1 = sP[ci[win+1]*3 + 1];
            float4 s2 = sP[ci[win+2]*3 + 2];
            a.x = fmaxf(a.x, s0.x + s1.x + s2.x);
            a.y = fmaxf(a.y, s0.y + s1.y + s2.y);
            a.z = fmaxf(a.z, s0.z + s1.z + s2.z);
            a.w = fmaxf(a.w, s0.w + s1.w + s2.w);
        }
        x[10]=a.x; x[11]=a.y; x[12]=a.z; x[13]=a.w;

        // 48 gate pre-activations -> sXG row (stride 50 halves: conflict-free)
        __half* st = &sXG[(wv2*Ssz + tid)*50];
        #pragma unroll
        for (int g=0; g<48; g++){
            float acc = sB[g];
            #pragma unroll
            for (int q=0; q<4; q++){
                float4 wvv = sW[g*4 + q];
                acc = fmaf(x[4*q+0], wvv.x, acc);
                acc = fmaf(x[4*q+1], wvv.y, acc);
                acc = fmaf(x[4*q+2], wvv.z, acc);
                acc = fmaf(x[4*q+3], wvv.w, acc);
            }
            st[g] = __float2half(acc);
        }
    }
    __syncthreads();   // tables dead below; sH aliases them

    // ---- Phase B: 4 warps = 2 sentences x 2 dirs; lane j<24 owns gate j ----
    {
        int sent = warp >> 1;
        int d    = warp & 1;
        int jc   = (lane < 24) ? lane : 0;
        bool is_g = (lane >= 12 && lane < 18);
        float sm = is_g ? 1.f : 0.5f;     // sigmoid(x) = 0.5*tanh(0.5x)+0.5
        float ab = is_g ? 0.f : 0.5f;

        const float* Whh = d ? Whh_b : Whh_f;
        float w0=__ldg(Whh+jc*6+0), w1=__ldg(Whh+jc*6+1), w2=__ldg(Whh+jc*6+2),
              w3=__ldg(Whh+jc*6+3), w4=__ldg(Whh+jc*6+4), w5=__ldg(Whh+jc*6+5);

        const __half* xgp = &sXG[sent*Ssz*50 + d*24];
        float* hst = sH + sent*Ssz*12 + d*6;

        float h0=0.f,h1=0.f,h2=0.f,h3=0.f,h4=0.f,h5=0.f,c=0.f;
        int s  = d ? (Ssz-1) : 0;
        int ds = d ? -1 : 1;

        float pf = __half2float(xgp[s*50 + jc]);
        #pragma unroll 4
        for (int t=0; t<Ssz; t++){
            float gcur = pf;
            if (t+1 < Ssz) pf = __half2float(xgp[(s+ds)*50 + jc]);  // one-ahead prefetch

            float g = fmaf(w0,h0,gcur);
            g = fmaf(w1,h1,g); g = fmaf(w2,h2,g); g = fmaf(w3,h3,g);
            g = fmaf(w4,h4,g); g = fmaf(w5,h5,g);
            float act = fmaf(sm, tanh_fast(g*sm), ab);

            float af = __shfl_sync(FULL, act, lane+6);
            float ag = __shfl_sync(FULL, act, lane+12);
            float ao = __shfl_sync(FULL, act, lane+18);
            c = fmaf(af, c, act*ag);
            float hj = ao * tanh_fast(c);

            h0=__shfl_sync(FULL,hj,0); h1=__shfl_sync(FULL,hj,1); h2=__shfl_sync(FULL,hj,2);
            h3=__shfl_sync(FULL,hj,3); h4=__shfl_sync(FULL,hj,4); h5=__shfl_sync(FULL,hj,5);

            if (lane < 6) hst[s*12 + lane] = hj;
            s += ds;
        }
    }
    __syncthreads();

    // ---- Phase C: tag linear + log_softmax, weights in registers ----
    float wt[5][12], bs[5];
    #pragma unroll
    for (int t5=0; t5<5; t5++){
        int j = lane + 32*t5;
        bool valid = (j < 135);
        bs[t5] = valid ? __ldg(bt + j) : -1e30f;   // exp(-1e30)=0, drops out of sum
        #pragma unroll
        for (int k=0;k<12;k++) wt[t5][k] = valid ? __ldg(Wt + j*12 + k) : 0.f;
    }

    int base = warp*64;
    #pragma unroll 2
    for (int it=0; it<64; it++){
        int p = base + it;                                // 0..255 over both sentences
        const float4* hp = (const float4*)(sH + p*12);    // 48B stride, aligned, broadcast
        float4 h0v = hp[0], h1v = hp[1], h2v = hp[2];
        float h[12] = {h0v.x,h0v.y,h0v.z,h0v.w, h1v.x,h1v.y,h1v.z,h1v.w,
                       h2v.x,h2v.y,h2v.z,h2v.w};

        // |v| bounded (|h|<1, small weights): safe to skip max-shift
        float tg[5]; float zs = 0.f;
        #pragma unroll
        for (int t5=0; t5<5; t5++){
            float v = bs[t5];
            #pragma unroll
            for (int k=0;k<12;k++) v = fmaf(h[k], wt[t5][k], v);
            tg[t5] = v;
            zs += __expf(v);
        }
        #pragma unroll
        for (int o=16;o>0;o>>=1) zs += __shfl_xor_sync(FULL, zs, o);
        float lse = __logf(zs);

        float* op = out + ((size_t)blk*2*Ssz + p)*135;
        #pragma unroll
        for (int t5=0; t5<5; t5++){
            int j = lane + 32*t5;
            if (j < 135) op[j] = tg[t5] - lse;
        }
    }
}

// ---------------- Launch ----------------
extern "C" void kernel_launch(void* const* d_in, const int* in_sizes, int n_in,
                              void* d_out, int out_size)
{
    const int *word_idx=nullptr,*char_idx=nullptr;
    const float *word_emb=nullptr,*char_emb=nullptr,*Wc=nullptr,*bc=nullptr,
        *Wih_f=nullptr,*Whh_f=nullptr,*b_f=nullptr,
        *Wih_b=nullptr,*Whh_b=nullptr,*b_b=nullptr,*Wt=nullptr,*bt=nullptr;
    for (int i=0;i<n_in;i++){
        int sz = in_sizes[i]; const void* p = d_in[i];
        switch (sz){
            case 131072:  word_idx=(const int*)p; break;          // [B,S]
            case 1835008: char_idx=(const int*)p; break;          // [B,S,LP]
            case 500000:  word_emb=(const float*)p; break;        // [V,WE]
            case 600:     char_emb=(const float*)p; break;        // [A,CE]
            case 72:      Wc=(const float*)p; break;              // [Lf,K*CE]
            case 4:       bc=(const float*)p; break;              // [Lf]
            case 336:     if(!Wih_f) Wih_f=(const float*)p; else Wih_b=(const float*)p; break;
            case 144:     if(!Whh_f) Whh_f=(const float*)p; else Whh_b=(const float*)p; break;
            case 24:      if(!b_f)   b_f  =(const float*)p; else b_b  =(const float*)p; break;
            case 1620:    Wt=(const float*)p; break;              // [T,2H]
            case 135:     bt=(const float*)p; break;              // [T]
        }
    }

    fused_tagger<<<Bsz/2, 128>>>(word_idx, char_idx, word_emb, char_emb,
                                 Wc, bc, Wih_f, b_f, Wih_b, b_b,
                                 Whh_f, Whh_b, Wt, bt, (float*)d_out);
    (void)out_size; (void)n_in;
}